// round 15
// baseline (speedup 1.0000x reference)
#include <cuda_runtime.h>
#include <cstdint>

using ull = unsigned long long;
#define NTHREADS 512

__device__ __forceinline__ void fma2(ull& d, ull a, ull b) {
    asm("fma.rn.f32x2 %0, %1, %2, %0;" : "+l"(d) : "l"(a), "l"(b));
}
__device__ __forceinline__ ull dup2(float x) {
    ull d; unsigned xi = __float_as_uint(x);
    asm("mov.b64 %0, {%1, %1};" : "=l"(d) : "r"(xi));
    return d;
}
__device__ __forceinline__ float ulo(ull v) { return __uint_as_float((unsigned)v); }
__device__ __forceinline__ float uhi(ull v) { return __uint_as_float((unsigned)(v >> 32)); }
__device__ __forceinline__ void cp_async8(void* dst, const void* src) {
    unsigned s = (unsigned)__cvta_generic_to_shared(dst);
    asm volatile("cp.async.ca.shared.global [%0], [%1], 8;" :: "r"(s), "l"(src));
}
__device__ __forceinline__ void cp_commit() { asm volatile("cp.async.commit_group;"); }
__device__ __forceinline__ void cp_wait1() { asm volatile("cp.async.wait_group 1;" ::: "memory"); }

// ---------------------------------------------------------------------------
// 0e: out[n,o] = sum_i x[n,i]*w[o,i] + bias[o];  I=O=128
// 512 thr / 16 warps. TILE=256 nodes, K-chunks of 64 (NC=2).
// warp: grp=warp>>1 owns outputs [16g,16g+16) (p=8 pairs); half=warp&1;
// lane owns nodes half*32+lane + 64q, q<4 (n=4).
// ---------------------------------------------------------------------------
__device__ void body_k0e(int cta, int ncta,
                         const float* __restrict__ x, const float* __restrict__ w,
                         const float* __restrict__ bias, float* __restrict__ out,
                         int N, float* sm) {
    constexpr int K = 128, TILE = 256, NC = 2, XROW = 68, WROW = 132;
    constexpr int WS = 128 * WROW;       // 16896 floats
    constexpr int XB = TILE * XROW;      // 17408 floats per buffer
    constexpr int CH = TILE * 32;        // 8192 8B ops per chunk (64 floats/node)

    float* ws = sm;
    float* xb0 = sm + WS;
    float* xb1 = sm + WS + XB;
    float* bs  = sm + WS + 2 * XB;

    int tid = threadIdx.x;
    for (int idx = tid; idx < 128 * 128; idx += NTHREADS)
        ws[(idx & 127) * WROW + (idx >> 7)] = w[idx];        // ws[i][o]
    if (tid < 128) bs[tid] = bias[tid];

    int warp = tid >> 5, lane = tid & 31;
    int grp  = warp >> 1;
    int nb   = (warp & 1) * 32 + lane;   // node base (0..63)

    int ntiles = (N + TILE - 1) / TILE;
    int nmy = (cta < ntiles) ? (ntiles - cta + ncta - 1) / ncta : 0;
    int steps = nmy * NC;

    // prefetch step s into dst
    auto prefetch = [&](int s, float* dst) {
        int tk = s >> 1, c = s & 1;
        long long base = (long long)(cta + tk * ncta) * TILE;
        const float* src = x + 64 * c;
        for (int ch = tid; ch < CH; ch += NTHREADS) {
            int nd = ch >> 5, cq = ch & 31;
            long long n = base + nd;
            if (n < N) cp_async8(dst + nd * XROW + cq * 2, src + n * K + cq * 2);
        }
    };

    if (steps > 0) prefetch(0, xb0);
    cp_commit();

    ull acc[4][8];
    for (int s = 0; s < steps; s++) {
        if (s + 1 < steps) prefetch(s + 1, (s & 1) ? xb0 : xb1);
        cp_commit();
        cp_wait1();
        __syncthreads();

        float* xa = (s & 1) ? xb1 : xb0;
        int c = s & 1;

        if (c == 0) {
            const ull* b2 = (const ull*)bs;
            #pragma unroll
            for (int q = 0; q < 4; q++)
                #pragma unroll
                for (int j = 0; j < 8; j++) acc[q][j] = b2[grp * 8 + j];
        }

        const float4* xr0 = (const float4*)(xa + (nb      ) * XROW);
        const float4* xr1 = (const float4*)(xa + (nb +  64) * XROW);
        const float4* xr2 = (const float4*)(xa + (nb + 128) * XROW);
        const float4* xr3 = (const float4*)(xa + (nb + 192) * XROW);
        const float* wsb = ws + 64 * c * WROW;

        #pragma unroll 4
        for (int k4 = 0; k4 < 16; k4++) {
            float xs[4][4];
            *(float4*)&xs[0][0] = xr0[k4];
            *(float4*)&xs[1][0] = xr1[k4];
            *(float4*)&xs[2][0] = xr2[k4];
            *(float4*)&xs[3][0] = xr3[k4];
            #pragma unroll
            for (int kk = 0; kk < 4; kk++) {
                const ulonglong2* wr =
                    (const ulonglong2*)(wsb + (k4 * 4 + kk) * WROW) + grp * 4;
                ulonglong2 u0 = wr[0], u1 = wr[1], u2 = wr[2], u3 = wr[3];
                #pragma unroll
                for (int q = 0; q < 4; q++) {
                    ull xd = dup2(xs[q][kk]);
                    fma2(acc[q][0], xd, u0.x); fma2(acc[q][1], xd, u0.y);
                    fma2(acc[q][2], xd, u1.x); fma2(acc[q][3], xd, u1.y);
                    fma2(acc[q][4], xd, u2.x); fma2(acc[q][5], xd, u2.y);
                    fma2(acc[q][6], xd, u3.x); fma2(acc[q][7], xd, u3.y);
                }
            }
        }

        if (c == NC - 1) {
            long long base = (long long)(cta + (s >> 1) * ncta) * TILE;
            #pragma unroll
            for (int q = 0; q < 4; q++) {
                long long n = base + nb + 64 * q;
                if (n < N) {
                    ulonglong2* d = (ulonglong2*)(out + n * 480 + grp * 16);
                    d[0] = make_ulonglong2(acc[q][0], acc[q][1]);
                    d[1] = make_ulonglong2(acc[q][2], acc[q][3]);
                    d[2] = make_ulonglong2(acc[q][4], acc[q][5]);
                    d[3] = make_ulonglong2(acc[q][6], acc[q][7]);
                }
            }
        }
        __syncthreads();
    }
}

// ---------------------------------------------------------------------------
// 1o: out[n,o,m] = sum_i x[n,i,m]*w[o,i,m];  I=O=64, M=3
// 512 thr / 16 warps. TILE=192 nodes, i-chunks of 16 (NC=4, 48 floats).
// warp: grp=warp>>1 owns outputs [8g,8g+8) (p=4 pairs); half=warp&1;
// lane owns nodes half*32+lane + 64q, q<3 (n=3).
// ---------------------------------------------------------------------------
__device__ void body_k1o(int cta, int ncta,
                         const float* __restrict__ x, const float* __restrict__ w,
                         float* __restrict__ out, int N, float* sm) {
    constexpr int K = 192, TILE = 192, NC = 4, XROW = 50, WROW = 68;
    constexpr int WS = 192 * WROW;       // 13056
    constexpr int XB = TILE * XROW;      // 9600
    constexpr int CH = TILE * 24;        // 4608 8B ops per chunk (48 floats/node)

    float* ws  = sm;
    float* xb0 = sm + WS;
    float* xb1 = sm + WS + XB;

    int tid = threadIdx.x;
    for (int idx = tid; idx < 64 * 192; idx += NTHREADS)
        ws[(idx % 192) * WROW + (idx / 192)] = w[idx];       // ws[i*3+m][o]

    int warp = tid >> 5, lane = tid & 31;
    int grp  = warp >> 1;
    int nb   = (warp & 1) * 32 + lane;

    int ntiles = (N + TILE - 1) / TILE;
    int nmy = (cta < ntiles) ? (ntiles - cta + ncta - 1) / ncta : 0;
    int steps = nmy * NC;

    auto prefetch = [&](int s, float* dst) {
        int tk = s >> 2, c = s & 3;
        long long base = (long long)(cta + tk * ncta) * TILE;
        const float* src = x + 48 * c;
        for (int ch = tid; ch < CH; ch += NTHREADS) {
            int nd = ch / 24, cq = ch % 24;
            long long n = base + nd;
            if (n < N) cp_async8(dst + nd * XROW + cq * 2, src + n * K + cq * 2);
        }
    };

    if (steps > 0) prefetch(0, xb0);
    cp_commit();

    ull acc[3][3][4];
    for (int s = 0; s < steps; s++) {
        if (s + 1 < steps) prefetch(s + 1, (s & 1) ? xb0 : xb1);
        cp_commit();
        cp_wait1();
        __syncthreads();

        float* xa = (s & 1) ? xb1 : xb0;
        int c = s & 3;

        if (c == 0) {
            #pragma unroll
            for (int q = 0; q < 3; q++)
                #pragma unroll
                for (int m = 0; m < 3; m++)
                    #pragma unroll
                    for (int p = 0; p < 4; p++) acc[q][m][p] = 0ull;
        }

        const float* xr0 = xa + (nb      ) * XROW;
        const float* xr1 = xa + (nb +  64) * XROW;
        const float* xr2 = xa + (nb + 128) * XROW;
        const float* wsb = ws + (16 * c * 3) * WROW;

        #pragma unroll 2
        for (int il = 0; il < 16; il += 2) {
            float xs[3][6];
            *(float2*)&xs[0][0] = *(const float2*)(xr0 + 3 * il);
            *(float2*)&xs[0][2] = *(const float2*)(xr0 + 3 * il + 2);
            *(float2*)&xs[0][4] = *(const float2*)(xr0 + 3 * il + 4);
            *(float2*)&xs[1][0] = *(const float2*)(xr1 + 3 * il);
            *(float2*)&xs[1][2] = *(const float2*)(xr1 + 3 * il + 2);
            *(float2*)&xs[1][4] = *(const float2*)(xr1 + 3 * il + 4);
            *(float2*)&xs[2][0] = *(const float2*)(xr2 + 3 * il);
            *(float2*)&xs[2][2] = *(const float2*)(xr2 + 3 * il + 2);
            *(float2*)&xs[2][4] = *(const float2*)(xr2 + 3 * il + 4);
            #pragma unroll
            for (int s2 = 0; s2 < 2; s2++)
                #pragma unroll
                for (int m = 0; m < 3; m++) {
                    const ulonglong2* wr =
                        (const ulonglong2*)(wsb + ((il + s2) * 3 + m) * WROW) + grp * 2;
                    ulonglong2 u0 = wr[0], u1 = wr[1];
                    #pragma unroll
                    for (int q = 0; q < 3; q++) {
                        ull v = dup2(xs[q][s2 * 3 + m]);
                        fma2(acc[q][m][0], v, u0.x); fma2(acc[q][m][1], v, u0.y);
                        fma2(acc[q][m][2], v, u1.x); fma2(acc[q][m][3], v, u1.y);
                    }
                }
        }

        if (c == NC - 1) {
            long long base = (long long)(cta + (s >> 2) * ncta) * TILE;
            #pragma unroll
            for (int q = 0; q < 3; q++) {
                long long n = base + nb + 64 * q;
                if (n < N) {
                    float4 y4[6];
                    float* y = (float*)y4;
                    #pragma unroll
                    for (int m = 0; m < 3; m++)
                        #pragma unroll
                        for (int p = 0; p < 4; p++) {
                            y[(2 * p) * 3 + m]     = ulo(acc[q][m][p]);
                            y[(2 * p + 1) * 3 + m] = uhi(acc[q][m][p]);
                        }
                    float4* d = (float4*)(out + n * 480 + 128 + 24 * grp);
                    #pragma unroll
                    for (int e = 0; e < 6; e++) d[e] = y4[e];
                }
            }
        }
        __syncthreads();
    }
}

// ---------------------------------------------------------------------------
// 2e: out[n,o,m] = sum_i x[n,i,m]*w[o,i,m];  I=O=32, M=5
// 512 thr / 16 warps. TILE=256 nodes, i-chunks of 16 (NC=2, 80 floats).
// warp: grp=warp>>2 owns outputs [8g,8g+8) (p=4 pairs); quar=warp&3;
// lane owns nodes quar*32+lane + 128q, q<2 (n=2).
// ---------------------------------------------------------------------------
__device__ void body_k2e(int cta, int ncta,
                         const float* __restrict__ x, const float* __restrict__ w,
                         float* __restrict__ out, int N, float* sm) {
    constexpr int K = 160, TILE = 256, NC = 2, XROW = 82, WROW = 36;
    constexpr int WS = 160 * WROW;       // 5760
    constexpr int XB = TILE * XROW;      // 20992
    constexpr int CH = TILE * 40;        // 10240 8B ops (80 floats/node)

    float* ws  = sm;
    float* xb0 = sm + WS;
    float* xb1 = sm + WS + XB;

    int tid = threadIdx.x;
    for (int idx = tid; idx < 32 * 160; idx += NTHREADS)
        ws[(idx % 160) * WROW + (idx / 160)] = w[idx];       // ws[i*5+m][o]

    int warp = tid >> 5, lane = tid & 31;
    int grp  = warp >> 2;
    int nb   = (warp & 3) * 32 + lane;   // 0..127

    int ntiles = (N + TILE - 1) / TILE;
    int nmy = (cta < ntiles) ? (ntiles - cta + ncta - 1) / ncta : 0;
    int steps = nmy * NC;

    auto prefetch = [&](int s, float* dst) {
        int tk = s >> 1, c = s & 1;
        long long base = (long long)(cta + tk * ncta) * TILE;
        const float* src = x + 80 * c;
        for (int ch = tid; ch < CH; ch += NTHREADS) {
            int nd = ch / 40, cq = ch % 40;
            long long n = base + nd;
            if (n < N) cp_async8(dst + nd * XROW + cq * 2, src + n * K + cq * 2);
        }
    };

    if (steps > 0) prefetch(0, xb0);
    cp_commit();

    ull acc[2][5][4];
    for (int s = 0; s < steps; s++) {
        if (s + 1 < steps) prefetch(s + 1, (s & 1) ? xb0 : xb1);
        cp_commit();
        cp_wait1();
        __syncthreads();

        float* xa = (s & 1) ? xb1 : xb0;
        int c = s & 1;

        if (c == 0) {
            #pragma unroll
            for (int q = 0; q < 2; q++)
                #pragma unroll
                for (int m = 0; m < 5; m++)
                    #pragma unroll
                    for (int p = 0; p < 4; p++) acc[q][m][p] = 0ull;
        }

        const float* xr0 = xa + (nb      ) * XROW;
        const float* xr1 = xa + (nb + 128) * XROW;
        const float* wsb = ws + (16 * c * 5) * WROW;

        #pragma unroll 2
        for (int il = 0; il < 16; il += 2) {
            float xs[2][10];
            #pragma unroll
            for (int u = 0; u < 5; u++) {
                *(float2*)&xs[0][2 * u] = *(const float2*)(xr0 + 5 * il + 2 * u);
                *(float2*)&xs[1][2 * u] = *(const float2*)(xr1 + 5 * il + 2 * u);
            }
            #pragma unroll
            for (int s2 = 0; s2 < 2; s2++)
                #pragma unroll
                for (int m = 0; m < 5; m++) {
                    const ulonglong2* wr =
                        (const ulonglong2*)(wsb + ((il + s2) * 5 + m) * WROW) + grp * 2;
                    ulonglong2 u0 = wr[0], u1 = wr[1];
                    #pragma unroll
                    for (int q = 0; q < 2; q++) {
                        ull v = dup2(xs[q][s2 * 5 + m]);
                        fma2(acc[q][m][0], v, u0.x); fma2(acc[q][m][1], v, u0.y);
                        fma2(acc[q][m][2], v, u1.x); fma2(acc[q][m][3], v, u1.y);
                    }
                }
        }

        if (c == NC - 1) {
            long long base = (long long)(cta + (s >> 1) * ncta) * TILE;
            #pragma unroll
            for (int q = 0; q < 2; q++) {
                long long n = base + nb + 128 * q;
                if (n < N) {
                    float4 y4[10];
                    float* y = (float*)y4;
                    #pragma unroll
                    for (int m = 0; m < 5; m++)
                        #pragma unroll
                        for (int p = 0; p < 4; p++) {
                            y[(2 * p) * 5 + m]     = ulo(acc[q][m][p]);
                            y[(2 * p + 1) * 5 + m] = uhi(acc[q][m][p]);
                        }
                    float4* d = (float4*)(out + n * 480 + 320 + 40 * grp);
                    #pragma unroll
                    for (int e = 0; e < 10; e++) d[e] = y4[e];
                }
            }
        }
        __syncthreads();
    }
}

// ---------------------------------------------------------------------------
// Fused persistent kernel
// ---------------------------------------------------------------------------
#define C0 64
#define C1 59
#define C2 29

__global__ __launch_bounds__(NTHREADS, 1)
void fused(const float* __restrict__ x0e, const float* __restrict__ x1o,
           const float* __restrict__ x2e, const float* __restrict__ w0e,
           const float* __restrict__ w1o, const float* __restrict__ w2e,
           const float* __restrict__ bias, float* __restrict__ out, int N) {
    extern __shared__ float sm[];
    int b = blockIdx.x;
    if (b < C0)            body_k0e(b, C0, x0e, w0e, bias, out, N, sm);
    else if (b < C0 + C1)  body_k1o(b - C0, C1, x1o, w1o, out, N, sm);
    else                   body_k2e(b - C0 - C1, C2, x2e, w2e, out, N, sm);
}

// ---------------------------------------------------------------------------
extern "C" void kernel_launch(void* const* d_in, const int* in_sizes, int n_in,
                              void* d_out, int out_size) {
    const float* x0e  = (const float*)d_in[0];
    const float* x1o  = (const float*)d_in[1];
    const float* x2e  = (const float*)d_in[2];
    const float* w0e  = (const float*)d_in[3];
    const float* w1o  = (const float*)d_in[4];
    const float* w2e  = (const float*)d_in[5];
    const float* bias = (const float*)d_in[6];
    float* out = (float*)d_out;
    int N = in_sizes[0] / 128;

    // largest body: k0e = (16896 + 2*17408 + 128)*4 = 207360 B
    int smem = (16896 + 2 * 17408 + 128) * 4;
    cudaFuncSetAttribute(fused, cudaFuncAttributeMaxDynamicSharedMemorySize, smem);

    fused<<<C0 + C1 + C2, NTHREADS, smem>>>(x0e, x1o, x2e, w0e, w1o, w2e, bias, out, N);
}

// round 16
// speedup vs baseline: 1.2057x; 1.2057x over previous
#include <cuda_runtime.h>
#include <cstdint>

using ull = unsigned long long;
#define NTHREADS 512

__device__ __forceinline__ void fma2(ull& d, ull a, ull b) {
    asm("fma.rn.f32x2 %0, %1, %2, %0;" : "+l"(d) : "l"(a), "l"(b));
}
__device__ __forceinline__ ull dup2(float x) {
    ull d; unsigned xi = __float_as_uint(x);
    asm("mov.b64 %0, {%1, %1};" : "=l"(d) : "r"(xi));
    return d;
}
__device__ __forceinline__ float ulo(ull v) { return __uint_as_float((unsigned)v); }
__device__ __forceinline__ float uhi(ull v) { return __uint_as_float((unsigned)(v >> 32)); }
__device__ __forceinline__ void cp_async16(void* dst, const void* src) {
    unsigned s = (unsigned)__cvta_generic_to_shared(dst);
    asm volatile("cp.async.cg.shared.global [%0], [%1], 16;" :: "r"(s), "l"(src));
}
__device__ __forceinline__ void cp_commit() { asm volatile("cp.async.commit_group;"); }
__device__ __forceinline__ void cp_wait1() { asm volatile("cp.async.wait_group 1;" ::: "memory"); }

// ---------------------------------------------------------------------------
// 0e: out[n,o] = sum_i x[n,i]*w[o,i] + bias[o];  I=O=128
// 512 thr. TILE=128. grp=warp>>1 owns outputs [16g,16g+16) (p=8);
// nb=(warp&1)*32+lane owns nodes nb, nb+64 (n=2). x via LDS.128.
// ---------------------------------------------------------------------------
__global__ __launch_bounds__(NTHREADS, 1)
void k0e(const float* __restrict__ x, const float* __restrict__ w,
         const float* __restrict__ bias, float* __restrict__ out, int N) {
    constexpr int K = 128, TILE = 128, XROW = 132, WROW = 132;
    constexpr int WS = 128 * WROW;       // 16896 floats
    constexpr int XB = TILE * XROW;      // 16896 floats
    constexpr int CH = TILE * (K / 4);   // 4096 16B ops/tile

    extern __shared__ float sm[];
    float* ws  = sm;
    float* xb0 = sm + WS;
    float* xb1 = sm + WS + XB;
    float* bs  = sm + WS + 2 * XB;

    int tid = threadIdx.x;
    for (int idx = tid; idx < 128 * 128; idx += NTHREADS)
        ws[(idx & 127) * WROW + (idx >> 7)] = w[idx];        // ws[i][o]
    if (tid < 128) bs[tid] = bias[tid];

    int warp = tid >> 5, lane = tid & 31;
    int grp  = warp >> 1;
    int nb   = (warp & 1) * 32 + lane;

    int ntiles = (N + TILE - 1) / TILE;
    int t0 = blockIdx.x;

    if (t0 < ntiles) {
        long long base = (long long)t0 * TILE;
        for (int c = tid; c < CH; c += NTHREADS) {
            int nd = c >> 5, cq = c & 31;
            long long n = base + nd;
            if (n < N) cp_async16(xb0 + nd * XROW + cq * 4, x + n * K + cq * 4);
        }
    }
    cp_commit();

    int par = 0;
    for (int t = t0; t < ntiles; t += gridDim.x, par ^= 1) {
        int tn = t + gridDim.x;
        if (tn < ntiles) {
            long long base = (long long)tn * TILE;
            float* dst = par ? xb0 : xb1;
            for (int c = tid; c < CH; c += NTHREADS) {
                int nd = c >> 5, cq = c & 31;
                long long n = base + nd;
                if (n < N) cp_async16(dst + nd * XROW + cq * 4, x + n * K + cq * 4);
            }
        }
        cp_commit();
        cp_wait1();
        __syncthreads();

        float* xa = par ? xb1 : xb0;
        const float4* xr0 = (const float4*)(xa + nb * XROW);
        const float4* xr1 = (const float4*)(xa + (nb + 64) * XROW);

        ull acc0[8], acc1[8];
        const ull* b2 = (const ull*)bs;
        #pragma unroll
        for (int j = 0; j < 8; j++) { acc0[j] = b2[grp * 8 + j]; acc1[j] = b2[grp * 8 + j]; }

        #pragma unroll 4
        for (int k4 = 0; k4 < K / 4; k4++) {
            float4 a = xr0[k4];
            float4 b = xr1[k4];
            float as[4] = {a.x, a.y, a.z, a.w};
            float bx[4] = {b.x, b.y, b.z, b.w};
            #pragma unroll
            for (int kk = 0; kk < 4; kk++) {
                const ulonglong2* wr =
                    (const ulonglong2*)(ws + (k4 * 4 + kk) * WROW) + grp * 4;
                ulonglong2 u0 = wr[0], u1 = wr[1], u2 = wr[2], u3 = wr[3];
                ull xd0 = dup2(as[kk]);
                fma2(acc0[0], xd0, u0.x); fma2(acc0[1], xd0, u0.y);
                fma2(acc0[2], xd0, u1.x); fma2(acc0[3], xd0, u1.y);
                fma2(acc0[4], xd0, u2.x); fma2(acc0[5], xd0, u2.y);
                fma2(acc0[6], xd0, u3.x); fma2(acc0[7], xd0, u3.y);
                ull xd1 = dup2(bx[kk]);
                fma2(acc1[0], xd1, u0.x); fma2(acc1[1], xd1, u0.y);
                fma2(acc1[2], xd1, u1.x); fma2(acc1[3], xd1, u1.y);
                fma2(acc1[4], xd1, u2.x); fma2(acc1[5], xd1, u2.y);
                fma2(acc1[6], xd1, u3.x); fma2(acc1[7], xd1, u3.y);
            }
        }

        long long base = (long long)t * TILE;
        long long n0 = base + nb, n1 = base + nb + 64;
        if (n0 < N) {
            ulonglong2* d = (ulonglong2*)(out + n0 * 480 + grp * 16);
            d[0] = make_ulonglong2(acc0[0], acc0[1]);
            d[1] = make_ulonglong2(acc0[2], acc0[3]);
            d[2] = make_ulonglong2(acc0[4], acc0[5]);
            d[3] = make_ulonglong2(acc0[6], acc0[7]);
        }
        if (n1 < N) {
            ulonglong2* d = (ulonglong2*)(out + n1 * 480 + grp * 16);
            d[0] = make_ulonglong2(acc1[0], acc1[1]);
            d[1] = make_ulonglong2(acc1[2], acc1[3]);
            d[2] = make_ulonglong2(acc1[4], acc1[5]);
            d[3] = make_ulonglong2(acc1[6], acc1[7]);
        }
        __syncthreads();
    }
}

// ---------------------------------------------------------------------------
// 1o: out[n,o,m] = sum_i x[n,i,m]*w[o,i,m];  I=O=64, M=3
// 512 thr. TILE=192 nodes, i-chunks of 16 (NC=4, 48 floats/node).
// grp=warp>>1 owns outputs [8g,8g+8) (p=4); nb=(warp&1)*32+lane, nodes nb+64q, q<3.
// ---------------------------------------------------------------------------
__global__ __launch_bounds__(NTHREADS, 1)
void k1o(const float* __restrict__ x, const float* __restrict__ w,
         float* __restrict__ out, int N) {
    constexpr int K = 192, TILE = 192, NC = 4, XROW = 52, WROW = 68;
    constexpr int WS = 192 * WROW;       // 13056
    constexpr int XB = TILE * XROW;      // 9984
    constexpr int CH = TILE * 12;        // 2304 16B ops per chunk (48 floats/node)

    extern __shared__ float sm[];
    float* ws  = sm;
    float* xb0 = sm + WS;
    float* xb1 = sm + WS + XB;

    int tid = threadIdx.x;
    for (int idx = tid; idx < 64 * 192; idx += NTHREADS)
        ws[(idx % 192) * WROW + (idx / 192)] = w[idx];       // ws[i*3+m][o]

    int warp = tid >> 5, lane = tid & 31;
    int grp  = warp >> 1;
    int nb   = (warp & 1) * 32 + lane;

    int ntiles = (N + TILE - 1) / TILE;
    int ncta = gridDim.x, cta = blockIdx.x;
    int nmy = (cta < ntiles) ? (ntiles - cta + ncta - 1) / ncta : 0;
    int steps = nmy * NC;

    auto prefetch = [&](int s, float* dst) {
        int tk = s >> 2, c = s & 3;
        long long base = (long long)(cta + tk * ncta) * TILE;
        const float* src = x + 48 * c;
        for (int ch = tid; ch < CH; ch += NTHREADS) {
            int nd = ch / 12, cq = ch % 12;
            long long n = base + nd;
            if (n < N) cp_async16(dst + nd * XROW + cq * 4, src + n * K + cq * 4);
        }
    };

    if (steps > 0) prefetch(0, xb0);
    cp_commit();

    ull acc[3][3][4];
    for (int s = 0; s < steps; s++) {
        if (s + 1 < steps) prefetch(s + 1, (s & 1) ? xb0 : xb1);
        cp_commit();
        cp_wait1();
        __syncthreads();

        float* xa = (s & 1) ? xb1 : xb0;
        int c = s & 3;

        if (c == 0) {
            #pragma unroll
            for (int q = 0; q < 3; q++)
                #pragma unroll
                for (int m = 0; m < 3; m++)
                    #pragma unroll
                    for (int p = 0; p < 4; p++) acc[q][m][p] = 0ull;
        }

        const float* xr0 = xa + (nb      ) * XROW;
        const float* xr1 = xa + (nb +  64) * XROW;
        const float* xr2 = xa + (nb + 128) * XROW;
        const float* wsb = ws + (16 * c * 3) * WROW;

        #pragma unroll 2
        for (int il = 0; il < 16; il += 2) {
            float xs[3][6];
            *(float2*)&xs[0][0] = *(const float2*)(xr0 + 3 * il);
            *(float2*)&xs[0][2] = *(const float2*)(xr0 + 3 * il + 2);
            *(float2*)&xs[0][4] = *(const float2*)(xr0 + 3 * il + 4);
            *(float2*)&xs[1][0] = *(const float2*)(xr1 + 3 * il);
            *(float2*)&xs[1][2] = *(const float2*)(xr1 + 3 * il + 2);
            *(float2*)&xs[1][4] = *(const float2*)(xr1 + 3 * il + 4);
            *(float2*)&xs[2][0] = *(const float2*)(xr2 + 3 * il);
            *(float2*)&xs[2][2] = *(const float2*)(xr2 + 3 * il + 2);
            *(float2*)&xs[2][4] = *(const float2*)(xr2 + 3 * il + 4);
            #pragma unroll
            for (int s2 = 0; s2 < 2; s2++)
                #pragma unroll
                for (int m = 0; m < 3; m++) {
                    const ulonglong2* wr =
                        (const ulonglong2*)(wsb + ((il + s2) * 3 + m) * WROW) + grp * 2;
                    ulonglong2 u0 = wr[0], u1 = wr[1];
                    #pragma unroll
                    for (int q = 0; q < 3; q++) {
                        ull v = dup2(xs[q][s2 * 3 + m]);
                        fma2(acc[q][m][0], v, u0.x); fma2(acc[q][m][1], v, u0.y);
                        fma2(acc[q][m][2], v, u1.x); fma2(acc[q][m][3], v, u1.y);
                    }
                }
        }

        if (c == NC - 1) {
            long long base = (long long)(cta + (s >> 2) * ncta) * TILE;
            #pragma unroll
            for (int q = 0; q < 3; q++) {
                long long n = base + nb + 64 * q;
                if (n < N) {
                    float4 y4[6];
                    float* y = (float*)y4;
                    #pragma unroll
                    for (int m = 0; m < 3; m++)
                        #pragma unroll
                        for (int p = 0; p < 4; p++) {
                            y[(2 * p) * 3 + m]     = ulo(acc[q][m][p]);
                            y[(2 * p + 1) * 3 + m] = uhi(acc[q][m][p]);
                        }
                    float4* d = (float4*)(out + n * 480 + 128 + 24 * grp);
                    #pragma unroll
                    for (int e = 0; e < 6; e++) d[e] = y4[e];
                }
            }
        }
        __syncthreads();
    }
}

// ---------------------------------------------------------------------------
// 2e: out[n,o,m] = sum_i x[n,i,m]*w[o,i,m];  I=O=32, M=5
// 512 thr. TILE=256 nodes, i-chunks of 16 (NC=2, 80 floats/node).
// grp=warp>>2 owns outputs [8g,8g+8) (p=4); nb=(warp&3)*32+lane, nodes nb+128q, q<2.
// ---------------------------------------------------------------------------
__global__ __launch_bounds__(NTHREADS, 1)
void k2e(const float* __restrict__ x, const float* __restrict__ w,
         float* __restrict__ out, int N) {
    constexpr int K = 160, TILE = 256, NC = 2, XROW = 84, WROW = 36;
    constexpr int WS = 160 * WROW;       // 5760
    constexpr int XB = TILE * XROW;      // 21504
    constexpr int CH = TILE * 20;        // 5120 16B ops per chunk (80 floats/node)

    extern __shared__ float sm[];
    float* ws  = sm;
    float* xb0 = sm + WS;
    float* xb1 = sm + WS + XB;

    int tid = threadIdx.x;
    for (int idx = tid; idx < 32 * 160; idx += NTHREADS)
        ws[(idx % 160) * WROW + (idx / 160)] = w[idx];       // ws[i*5+m][o]

    int warp = tid >> 5, lane = tid & 31;
    int grp  = warp >> 2;
    int nb   = (warp & 3) * 32 + lane;   // 0..127

    int ntiles = (N + TILE - 1) / TILE;
    int ncta = gridDim.x, cta = blockIdx.x;
    int nmy = (cta < ntiles) ? (ntiles - cta + ncta - 1) / ncta : 0;
    int steps = nmy * NC;

    auto prefetch = [&](int s, float* dst) {
        int tk = s >> 1, c = s & 1;
        long long base = (long long)(cta + tk * ncta) * TILE;
        const float* src = x + 80 * c;
        for (int ch = tid; ch < CH; ch += NTHREADS) {
            int nd = ch / 20, cq = ch % 20;
            long long n = base + nd;
            if (n < N) cp_async16(dst + nd * XROW + cq * 4, src + n * K + cq * 4);
        }
    };

    if (steps > 0) prefetch(0, xb0);
    cp_commit();

    ull acc[2][5][4];
    for (int s = 0; s < steps; s++) {
        if (s + 1 < steps) prefetch(s + 1, (s & 1) ? xb0 : xb1);
        cp_commit();
        cp_wait1();
        __syncthreads();

        float* xa = (s & 1) ? xb1 : xb0;
        int c = s & 1;

        if (c == 0) {
            #pragma unroll
            for (int q = 0; q < 2; q++)
                #pragma unroll
                for (int m = 0; m < 5; m++)
                    #pragma unroll
                    for (int p = 0; p < 4; p++) acc[q][m][p] = 0ull;
        }

        const float* xr0 = xa + (nb      ) * XROW;
        const float* xr1 = xa + (nb + 128) * XROW;
        const float* wsb = ws + (16 * c * 5) * WROW;

        #pragma unroll 2
        for (int il = 0; il < 16; il += 2) {
            float xs[2][10];
            #pragma unroll
            for (int u = 0; u < 5; u++) {
                *(float2*)&xs[0][2 * u] = *(const float2*)(xr0 + 5 * il + 2 * u);
                *(float2*)&xs[1][2 * u] = *(const float2*)(xr1 + 5 * il + 2 * u);
            }
            #pragma unroll
            for (int s2 = 0; s2 < 2; s2++)
                #pragma unroll
                for (int m = 0; m < 5; m++) {
                    const ulonglong2* wr =
                        (const ulonglong2*)(wsb + ((il + s2) * 5 + m) * WROW) + grp * 2;
                    ulonglong2 u0 = wr[0], u1 = wr[1];
                    #pragma unroll
                    for (int q = 0; q < 2; q++) {
                        ull v = dup2(xs[q][s2 * 5 + m]);
                        fma2(acc[q][m][0], v, u0.x); fma2(acc[q][m][1], v, u0.y);
                        fma2(acc[q][m][2], v, u1.x); fma2(acc[q][m][3], v, u1.y);
                    }
                }
        }

        if (c == NC - 1) {
            long long base = (long long)(cta + (s >> 1) * ncta) * TILE;
            #pragma unroll
            for (int q = 0; q < 2; q++) {
                long long n = base + nb + 128 * q;
                if (n < N) {
                    float4 y4[10];
                    float* y = (float*)y4;
                    #pragma unroll
                    for (int m = 0; m < 5; m++)
                        #pragma unroll
                        for (int p = 0; p < 4; p++) {
                            y[(2 * p) * 5 + m]     = ulo(acc[q][m][p]);
                            y[(2 * p + 1) * 5 + m] = uhi(acc[q][m][p]);
                        }
                    float4* d = (float4*)(out + n * 480 + 320 + 40 * grp);
                    #pragma unroll
                    for (int e = 0; e < 10; e++) d[e] = y4[e];
                }
            }
        }
        __syncthreads();
    }
}

// ---------------------------------------------------------------------------
extern "C" void kernel_launch(void* const* d_in, const int* in_sizes, int n_in,
                              void* d_out, int out_size) {
    const float* x0e  = (const float*)d_in[0];
    const float* x1o  = (const float*)d_in[1];
    const float* x2e  = (const float*)d_in[2];
    const float* w0e  = (const float*)d_in[3];
    const float* w1o  = (const float*)d_in[4];
    const float* w2e  = (const float*)d_in[5];
    const float* bias = (const float*)d_in[6];
    float* out = (float*)d_out;
    int N = in_sizes[0] / 128;

    int smem0 = (16896 + 2 * 16896 + 128) * 4;  // 203264 B
    int smem1 = (13056 + 2 * 9984) * 4;         // 132096 B
    int smem2 = (5760  + 2 * 21504) * 4;        // 195072 B

    cudaFuncSetAttribute(k0e, cudaFuncAttributeMaxDynamicSharedMemorySize, smem0);
    cudaFuncSetAttribute(k1o, cudaFuncAttributeMaxDynamicSharedMemorySize, smem1);
    cudaFuncSetAttribute(k2e, cudaFuncAttributeMaxDynamicSharedMemorySize, smem2);

    k0e<<<152, NTHREADS, smem0>>>(x0e, w0e, bias, out, N);
    k1o<<<152, NTHREADS, smem1>>>(x1o, w1o, out, N);
    k2e<<<152, NTHREADS, smem2>>>(x2e, w2e, out, N);
}